// round 13
// baseline (speedup 1.0000x reference)
#include <cuda_runtime.h>
#include <stdint.h>

#define NT 32768
#define DIM 512
#define NE 8192

#define TILE_M 128
#define TILE_N 128
#define NKB32 (DIM / 32)      // 16 k32 fragment blocks
#define NITER (DIM / 128)     // 4 mainloop iterations (k128 per stage)
#define NBY (NT / TILE_M)     // 256
#define NBX (NE / TILE_N)     // 64

#define CAP 64
#define MARGIN 16.0f          // ~23 sigma of int8 dist-error difference

// smem: [0,1024) smin u64[128]; [1024,...) 3 stages (A 16KB + B 16KB) / dist tile [col][132]
#define SM_SMIN_OFF 0
#define SM_DATA_OFF 1024
#define STAGE_BYTES 32768
#define SMEM_TOTAL (1024 + 3 * STAGE_BYTES)   // 99328; dist tile 128*132*4=67584 fits

// ---- device scratch ----
__device__ unsigned long long g_rowmin[NT];
__device__ float g_xnorm[NT];
__device__ float g_enorm[NE];
__device__ float g_sxs[NT];      // per-row scale of X (max/127)
__device__ float g_sxi[NT];      // 127/max (0 if max==0)
__device__ float g_ses[NE];      // per-col scale of E
__device__ float g_sei[NE];
__device__ float g_embedT[(size_t)NE * DIM];              // 16 MB
__device__ float g_rowloss[NT];
__device__ int g_candcnt[NT];
__device__ int g_candbuf[(size_t)NT * CAP];               // 8 MB
__device__ uint4 XA[(size_t)NBY * NKB32 * 256];           // 16.8 MB int8 frag-ordered
__device__ uint4 EB[(size_t)NBX * NKB32 * 256];           // 4.2 MB int8 frag-ordered

__device__ __forceinline__ void mma_s8(int* d, const uint32_t* a, const uint32_t* b) {
    asm volatile("mma.sync.aligned.m16n8k32.row.col.s32.s8.s8.s32 "
                 "{%0,%1,%2,%3}, {%4,%5,%6,%7}, {%8,%9}, {%0,%1,%2,%3};"
                 : "+r"(d[0]), "+r"(d[1]), "+r"(d[2]), "+r"(d[3])
                 : "r"(a[0]), "r"(a[1]), "r"(a[2]), "r"(a[3]), "r"(b[0]), "r"(b[1]));
}
__device__ __forceinline__ uint32_t smem_u32(const void* p) {
    uint32_t a;
    asm("{ .reg .u64 t; cvta.to.shared.u64 t, %1; cvt.u32.u64 %0, t; }" : "=r"(a) : "l"(p));
    return a;
}
__device__ __forceinline__ int q8(float x, float inv) {
    int q = __float2int_rn(x * inv);
    return q > 127 ? 127 : (q < -127 ? -127 : q);
}
__device__ __forceinline__ uint32_t pack4(int q0, int q1, int q2, int q3) {
    return (uint32_t)(q0 & 0xFF) | ((uint32_t)(q1 & 0xFF) << 8) |
           ((uint32_t)(q2 & 0xFF) << 16) | ((uint32_t)(q3 & 0xFF) << 24);
}
#define CP_ASYNC16(sa, g) asm volatile("cp.async.cg.shared.global [%0], [%1], 16;" :: "r"(sa), "l"(g))
#define CP_COMMIT()       asm volatile("cp.async.commit_group;")
#define CP_WAIT2()        asm volatile("cp.async.wait_group 2;")
#define CP_WAIT0()        asm volatile("cp.async.wait_group 0;")

// ---- launch 1: transpose + init + xnorm/xscale + enorm/escale ----
__global__ void misc_prep_kernel(const float* __restrict__ X, const float* __restrict__ E) {
    const int b = blockIdx.x;
    const int tid = threadIdx.x;
    if (b < 4096) {
        __shared__ float t[32][33];
        const int j0 = (b & 255) * 32, d0 = (b >> 8) * 32;
        const int tx = tid & 31, ty = tid >> 5;
        #pragma unroll
        for (int r = 0; r < 32; r += 8)
            t[ty + r][tx] = E[(size_t)(d0 + ty + r) * NE + j0 + tx];
        __syncthreads();
        #pragma unroll
        for (int r = 0; r < 32; r += 8)
            g_embedT[(size_t)(j0 + ty + r) * DIM + d0 + tx] = t[tx][ty + r];
    } else if (b < 4224) {
        const int i = (b - 4096) * 256 + tid;
        g_rowmin[i] = 0xFFFFFFFFFFFFFFFFULL;
        g_candcnt[i] = 0;
    } else if (b < 8320) {
        const int row = (b - 4224) * 8 + (tid >> 5);
        const int lane = tid & 31;
        const float4* xr = (const float4*)(X + (size_t)row * DIM);
        float s = 0.f, m = 0.f;
        #pragma unroll
        for (int i = lane; i < DIM / 4; i += 32) {
            float4 v = xr[i];
            s += v.x * v.x + v.y * v.y + v.z * v.z + v.w * v.w;
            m = fmaxf(m, fmaxf(fmaxf(fabsf(v.x), fabsf(v.y)), fmaxf(fabsf(v.z), fabsf(v.w))));
        }
        #pragma unroll
        for (int o = 16; o; o >>= 1) {
            s += __shfl_down_sync(0xffffffffu, s, o);
            m = fmaxf(m, __shfl_down_sync(0xffffffffu, m, o));
        }
        if (lane == 0) {
            g_xnorm[row] = s;
            g_sxs[row] = m * (1.f / 127.f);
            g_sxi[row] = m > 0.f ? 127.f / m : 0.f;
        }
    } else {
        const int j = (b - 8320) * 256 + tid;
        float s = 0.f, m = 0.f;
        for (int d = 0; d < DIM; ++d) {
            float v = E[(size_t)d * NE + j];
            s += v * v;
            m = fmaxf(m, fabsf(v));
        }
        g_enorm[j] = s;
        g_ses[j] = m * (1.f / 127.f);
        g_sei[j] = m > 0.f ? 127.f / m : 0.f;
    }
}

// ---- launch 2: X -> int8 fragment-ordered XA ----
// per k32 block: 8 units (wm*4+mi), uint4 = (a0,a1,a2,a3) of m16n8k32 s8 A-fragment
__global__ void prep_x_kernel(const float* __restrict__ X) {
    const int by = blockIdx.x >> 4, kb = blockIdx.x & 15;
    const int lane = threadIdx.x & 31;
    const int lq = lane >> 2, lr = lane & 3;
    #pragma unroll
    for (int h = 0; h < 2; h++) {
        const int unit = (threadIdx.x >> 5) + h * 4;    // 0..7
        const int wm = unit >> 2, mi = unit & 3;
        const int r0 = by * TILE_M + wm * 64 + mi * 16 + lq;
        const int k0 = kb * 32 + 4 * lr;
        const float* xr0 = X + (size_t)r0 * DIM;
        const float* xr8 = X + (size_t)(r0 + 8) * DIM;
        const float i0 = g_sxi[r0], i8 = g_sxi[r0 + 8];
        float4 v0 = *(const float4*)(xr0 + k0);
        float4 v8 = *(const float4*)(xr8 + k0);
        float4 w0 = *(const float4*)(xr0 + k0 + 16);
        float4 w8 = *(const float4*)(xr8 + k0 + 16);
        uint4 v;
        v.x = pack4(q8(v0.x, i0), q8(v0.y, i0), q8(v0.z, i0), q8(v0.w, i0));
        v.y = pack4(q8(v8.x, i8), q8(v8.y, i8), q8(v8.z, i8), q8(v8.w, i8));
        v.z = pack4(q8(w0.x, i0), q8(w0.y, i0), q8(w0.z, i0), q8(w0.w, i0));
        v.w = pack4(q8(w8.x, i8), q8(w8.y, i8), q8(w8.z, i8), q8(w8.w, i8));
        XA[((size_t)by * NKB32 + kb) * 256 + unit * 32 + lane] = v;
    }
}

// ---- launch 3: E -> int8 fragment-ordered EB ----
// per k32 block: 8 units (wn*4+njq), uint4 = (b0,b1 of nj=2njq; b0,b1 of nj=2njq+1)
__global__ void prep_e_kernel(const float* __restrict__ E) {
    const int bx = blockIdx.x >> 4, kb = blockIdx.x & 15;
    const int lane = threadIdx.x & 31;
    const int lq = lane >> 2, lr = lane & 3;
    #pragma unroll
    for (int h = 0; h < 2; h++) {
        const int unit = (threadIdx.x >> 5) + h * 4;    // 0..7
        const int wn = unit >> 2, njq = unit & 3;
        const int ce = bx * TILE_N + wn * 64 + (2 * njq) * 8 + lq;
        const int co = ce + 8;
        const int k0 = kb * 32 + 4 * lr;
        const float ie = g_sei[ce], io = g_sei[co];
        uint4 v;
        v.x = pack4(q8(E[(size_t)k0 * NE + ce], ie), q8(E[(size_t)(k0 + 1) * NE + ce], ie),
                    q8(E[(size_t)(k0 + 2) * NE + ce], ie), q8(E[(size_t)(k0 + 3) * NE + ce], ie));
        v.y = pack4(q8(E[(size_t)(k0 + 16) * NE + ce], ie), q8(E[(size_t)(k0 + 17) * NE + ce], ie),
                    q8(E[(size_t)(k0 + 18) * NE + ce], ie), q8(E[(size_t)(k0 + 19) * NE + ce], ie));
        v.z = pack4(q8(E[(size_t)k0 * NE + co], io), q8(E[(size_t)(k0 + 1) * NE + co], io),
                    q8(E[(size_t)(k0 + 2) * NE + co], io), q8(E[(size_t)(k0 + 3) * NE + co], io));
        v.w = pack4(q8(E[(size_t)(k0 + 16) * NE + co], io), q8(E[(size_t)(k0 + 17) * NE + co], io),
                    q8(E[(size_t)(k0 + 18) * NE + co], io), q8(E[(size_t)(k0 + 19) * NE + co], io));
        EB[((size_t)bx * NKB32 + kb) * 256 + unit * 32 + lane] = v;
    }
}

// ---- launch 4: s8 IMMA GEMM 128x128, 4 warps of 64x64, k128 stages, 2 CTA/SM ----
__device__ __forceinline__ void issue_stage(uint32_t sm_stage, const uint4* ga,
                                            const uint4* gb, int tid) {
    #pragma unroll
    for (int c = 0; c < 8; c++)
        CP_ASYNC16(sm_stage + (tid + c * 128) * 16, ga + tid + c * 128);
    #pragma unroll
    for (int c = 0; c < 8; c++)
        CP_ASYNC16(sm_stage + 16384 + (tid + c * 128) * 16, gb + tid + c * 128);
    CP_COMMIT();
}

__global__ void __launch_bounds__(128, 2) gemm_mma_kernel(float* __restrict__ distp) {
    extern __shared__ char smraw[];
    unsigned long long* smin = (unsigned long long*)(smraw + SM_SMIN_OFF);
    float* sdata = (float*)(smraw + SM_DATA_OFF);
    const uint32_t smb = smem_u32(smraw) + SM_DATA_OFF;

    const int tid = threadIdx.x;
    const int wid = tid >> 5;
    const int lane = tid & 31;
    const int wm = wid & 1;          // 2 warp-rows of 64
    const int wn = wid >> 1;         // 2 warp-cols of 64
    const int browg = blockIdx.y * TILE_M;
    const int bcolg = blockIdx.x * TILE_N;
    const int lq = lane >> 2;
    const int lr = lane & 3;

    // per iteration consumes 4 k32 blocks = 1024 uint4 of A and of B
    const uint4* ga = XA + (size_t)blockIdx.y * NKB32 * 256;
    const uint4* gb = EB + (size_t)blockIdx.x * NKB32 * 256;

    int d[4][8][4];
    #pragma unroll
    for (int mi = 0; mi < 4; mi++)
        #pragma unroll
        for (int nj = 0; nj < 8; nj++)
            #pragma unroll
            for (int c = 0; c < 4; c++) d[mi][nj][c] = 0;

    issue_stage(smb, ga, gb, tid);
    issue_stage(smb + STAGE_BYTES, ga + 1024, gb + 1024, tid);

    const uint32_t abase = (uint32_t)(wm * 4 * 32 + lane) * 16;   // + kh*4096 + mi*512
    const uint32_t bbase = (uint32_t)(wn * 4 * 32 + lane) * 16;   // + 16384 + kh*4096 + njq*512

    #pragma unroll 1
    for (int i = 0; i < NITER; ++i) {
        if (i + 2 < NITER)
            issue_stage(smb + ((i + 2) % 3) * STAGE_BYTES,
                        ga + (size_t)(i + 2) * 1024, gb + (size_t)(i + 2) * 1024, tid);
        CP_WAIT2();
        __syncthreads();

        const char* stg = (const char*)sdata + (i % 3) * STAGE_BYTES;
        #pragma unroll
        for (int kh = 0; kh < 4; ++kh) {
            const char* ah = stg + kh * 4096;
            const char* bhh = stg + 16384 + kh * 4096;
            uint32_t bh[8][2];
            #pragma unroll
            for (int njq = 0; njq < 4; njq++) {
                const uint4 p = *(const uint4*)(bhh + bbase + njq * 512);
                bh[2 * njq][0] = p.x; bh[2 * njq][1] = p.y;
                bh[2 * njq + 1][0] = p.z; bh[2 * njq + 1][1] = p.w;
            }
            #pragma unroll
            for (int mi = 0; mi < 4; mi++) {
                const uint4 a4 = *(const uint4*)(ah + abase + mi * 512);
                uint32_t ar[4] = {a4.x, a4.y, a4.z, a4.w};
                #pragma unroll
                for (int nj = 0; nj < 8; nj++)
                    mma_s8(d[mi][nj], ar, bh[nj]);
            }
        }
        __syncthreads();
    }
    CP_WAIT0();

    // ---- epilogue: dist tile + per-row argmin ----
    smin[tid] = 0xFFFFFFFFFFFFFFFFULL;
    __syncthreads();

    float* sd = sdata;   // [col][132]
    float en8[8][2], se8[8][2];
    #pragma unroll
    for (int nj = 0; nj < 8; nj++)
        #pragma unroll
        for (int cc = 0; cc < 2; cc++) {
            const int col = bcolg + wn * 64 + nj * 8 + 2 * lr + cc;
            en8[nj][cc] = g_enorm[col];
            se8[nj][cc] = g_ses[col];
        }

    #pragma unroll
    for (int mi = 0; mi < 4; mi++) {
        #pragma unroll
        for (int h = 0; h < 2; h++) {
            const int row_local = wm * 64 + mi * 16 + lq + h * 8;
            const int grow = browg + row_local;
            const float xn = g_xnorm[grow];
            const float sx2 = -2.f * g_sxs[grow];
            float best = 3.4e38f;
            int bcol = NE;
            #pragma unroll
            for (int nj = 0; nj < 8; nj++) {
                #pragma unroll
                for (int cc = 0; cc < 2; cc++) {
                    const int col_local = wn * 64 + nj * 8 + 2 * lr + cc;
                    const float dval =
                        fmaf(sx2 * se8[nj][cc], (float)d[mi][nj][h * 2 + cc], xn) + en8[nj][cc];
                    sd[col_local * 132 + row_local] = dval;
                    if (dval < best) { best = dval; bcol = bcolg + col_local; }
                }
            }
            atomicMin(&smin[row_local],
                      ((unsigned long long)__float_as_uint(best) << 32) | (unsigned)bcol);
        }
    }
    __syncthreads();

    atomicMin(&g_rowmin[browg + tid], smin[tid]);
    __syncthreads();

    // ---- candidate capture vs running global min (superset of final-margin set) ----
    {
        const int grow = browg + tid;   // 1 thread per row
        const unsigned long long cur = atomicMin(&g_rowmin[grow], 0xFFFFFFFFFFFFFFFFULL);
        const float thr = __uint_as_float((unsigned)(cur >> 32)) + MARGIN;
        #pragma unroll 4
        for (int c = 0; c < TILE_N; ++c) {
            const float v = sd[c * 132 + tid];
            if (v <= thr) {
                const int s = atomicAdd(&g_candcnt[grow], 1);
                if (s < CAP) g_candbuf[(size_t)grow * CAP + s] = bcolg + c;
            }
        }
    }
    __syncthreads();

    if (distp) {
        float* dbase = distp + (size_t)browg * NE + bcolg;
        #pragma unroll 4
        for (int j = 0; j < TILE_M; ++j)
            dbase[(size_t)j * NE + tid] = sd[tid * 132 + j];
    }
}

// ---- launch 5: exact fp32 rescore over captured candidates ----
__global__ void rescore_kernel(const float* __restrict__ X,
                               const float* __restrict__ distp) {
    const int row = blockIdx.x;
    const int tid = threadIdx.x;   // 128
    __shared__ int cand[CAP];
    __shared__ int scount;
    __shared__ float red[128];
    __shared__ unsigned long long sbest;

    int n = g_candcnt[row];
    if (n <= CAP) {
        for (int i = tid; i < n; i += 128) cand[i] = g_candbuf[(size_t)row * CAP + i];
        if (tid == 0) sbest = 0xFFFFFFFFFFFFFFFFULL;
        __syncthreads();
    } else {
        if (tid == 0) { scount = 0; sbest = 0xFFFFFFFFFFFFFFFFULL; }
        __syncthreads();
        const float thr = __uint_as_float((unsigned)(g_rowmin[row] >> 32)) + MARGIN;
        if (distp) {
            const float* dr = distp + (size_t)row * NE;
            for (int i = tid; i < NE; i += 128) {
                if (dr[i] <= thr) {
                    const int s = atomicAdd(&scount, 1);
                    if (s < CAP) cand[s] = i;
                }
            }
        } else if (tid == 0) scount = 0;
        __syncthreads();
        n = scount < CAP ? scount : CAP;
    }

    const float xn = g_xnorm[row];
    const float4 xv = ((const float4*)(X + (size_t)row * DIM))[tid];
    for (int c = 0; c < n; ++c) {
        const int col = cand[c];
        const float4 ev = ((const float4*)(g_embedT + (size_t)col * DIM))[tid];
        red[tid] = xv.x * ev.x + xv.y * ev.y + xv.z * ev.z + xv.w * ev.w;
        __syncthreads();
        #pragma unroll
        for (int s = 64; s; s >>= 1) {
            if (tid < s) red[tid] += red[tid + s];
            __syncthreads();
        }
        if (tid == 0) {
            const float dv = fmaf(-2.f, red[0], xn) + g_enorm[col];
            const unsigned long long pk =
                ((unsigned long long)__float_as_uint(dv) << 32) | (unsigned)col;
            if (pk < sbest) sbest = pk;
        }
        __syncthreads();
    }
    if (tid == 0 && n > 0) g_rowmin[row] = sbest;
}

// ---- launch 6: gather quantize rows, ind, per-row loss ----
__global__ void gather_kernel(const float* __restrict__ X,
                              float* __restrict__ qp, float* __restrict__ indp) {
    const int row = blockIdx.x;
    const int tid = threadIdx.x;   // 128
    const unsigned long long pk = g_rowmin[row];
    const unsigned ind = (unsigned)(pk & 0xFFFFFFFFu);
    if (indp && tid == 0) indp[row] = (float)ind;

    const float4 q = ((const float4*)(g_embedT + (size_t)ind * DIM))[tid];
    const float4 x = ((const float4*)(X + (size_t)row * DIM))[tid];

    if (qp) {
        float4 o;
        o.x = x.x + (q.x - x.x); o.y = x.y + (q.y - x.y);
        o.z = x.z + (q.z - x.z); o.w = x.w + (q.w - x.w);
        ((float4*)(qp + (size_t)row * DIM))[tid] = o;
    }
    float dx = x.x - q.x, dy = x.y - q.y, dz = x.z - q.z, dw = x.w - q.w;
    float ls = dx * dx + dy * dy + dz * dz + dw * dw;
    __shared__ float red[128];
    red[tid] = ls;
    __syncthreads();
    #pragma unroll
    for (int s = 64; s; s >>= 1) {
        if (tid < s) red[tid] += red[tid + s];
        __syncthreads();
    }
    if (tid == 0) g_rowloss[row] = red[0];
}

__global__ void loss_kernel(float* __restrict__ lossp) {
    __shared__ float red[512];
    const int tid = threadIdx.x;
    float s = 0.f;
    for (int i = tid; i < NT; i += 512) s += g_rowloss[i];
    red[tid] = s;
    __syncthreads();
    #pragma unroll
    for (int st = 256; st; st >>= 1) {
        if (tid < st) red[tid] += red[tid + st];
        __syncthreads();
    }
    if (tid == 0) *lossp = red[0] * (1.0f / ((float)NT * (float)DIM));
}

extern "C" void kernel_launch(void* const* d_in, const int* in_sizes, int n_in,
                              void* d_out, int out_size) {
    const float* X = (const float*)d_in[0];
    const float* E = (const float*)d_in[1];
    float* out = (float*)d_out;

    const long long QN = (long long)NT * DIM;
    const long long DN = (long long)NT * NE;
    const long long OS = (long long)out_size;

    float *qp = 0, *indp = 0, *lossp = 0, *distp = 0;
    if (OS == QN + NT + 1 + DN) {
        qp = out; indp = out + QN; lossp = out + QN + NT; distp = out + QN + NT + 1;
    } else if (OS == QN) { qp = out;
    } else if (OS == DN) { distp = out;
    } else if (OS == NT) { indp = out;
    } else if (OS == 1)  { lossp = out;
    } else if (OS == QN + NT + 1) { qp = out; indp = out + QN; lossp = out + QN + NT;
    } else {
        if (OS >= QN) qp = out;
        if (OS >= QN + NT) indp = out + QN;
        if (OS >= QN + NT + 1) lossp = out + QN + NT;
        if (OS >= QN + NT + 1 + DN) distp = out + QN + NT + 1;
    }

    cudaFuncSetAttribute(gemm_mma_kernel, cudaFuncAttributeMaxDynamicSharedMemorySize, SMEM_TOTAL);

    misc_prep_kernel<<<8352, 256>>>(X, E);                       // 1 (scales before prep)
    prep_x_kernel<<<NBY * NKB32, 128>>>(X);                      // 2
    prep_e_kernel<<<NBX * NKB32, 128>>>(E);                      // 3
    gemm_mma_kernel<<<dim3(NBX, NBY), 128, SMEM_TOTAL>>>(distp); // 4 (ncu slot)
    rescore_kernel<<<NT, 128>>>(X, distp);                       // 5
    gather_kernel<<<NT, 128>>>(X, qp, indp);                     // 6
    if (lossp) loss_kernel<<<1, 512>>>(lossp);                   // 7
}

// round 14
// speedup vs baseline: 2.1976x; 2.1976x over previous
#include <cuda_runtime.h>
#include <cuda_bf16.h>
#include <stdint.h>

#define NT 32768
#define DIM 512
#define NE 8192

#define TILE_M 128
#define TILE_N 128
#define NKB32 (DIM / 32)      // 16 k32 fragment blocks
#define NITER (DIM / 64)      // 8 mainloop iterations (k64 per stage)
#define NBY (NT / TILE_M)     // 256
#define NBX (NE / TILE_N)     // 64

#define CAP 64
#define MARGIN 4.0f           // ~22 sigma of bf16 dist-error difference

// smem: [0,1024) smin u64[128]; [1024,...) 2 stages (A 16KB + B 16KB) / dist tile [col][132]
#define SM_SMIN_OFF 0
#define SM_DATA_OFF 1024
#define STAGE_BYTES 32768
#define SMEM_TOTAL (1024 + TILE_N * 132 * 4)   // 68608 >= 1024 + 2*32768 (66560)

// ---- device scratch ----
__device__ unsigned long long g_rowmin[NT];
__device__ float g_xnorm[NT];
__device__ float g_enorm[NE];
__device__ float g_embedT[(size_t)NE * DIM];              // 16 MB
__device__ float g_rowloss[NT];
__device__ int g_candcnt[NT];
__device__ int g_candbuf[(size_t)NT * CAP];               // 8 MB
__device__ uint4 XA[(size_t)NBY * NKB32 * 512];           // 33.5 MB bf16 frag-ordered
__device__ uint4 EB[(size_t)NBX * NKB32 * 512];           // 8.4 MB bf16 frag-ordered

__device__ __forceinline__ uint32_t bf16x2(float lo, float hi) {
    uint32_t r;
    asm("cvt.rn.bf16x2.f32 %0, %1, %2;" : "=r"(r) : "f"(hi), "f"(lo));
    return r;
}
__device__ __forceinline__ void mma_bf16(float* d, const uint32_t* a, const uint32_t* b) {
    asm volatile("mma.sync.aligned.m16n8k16.row.col.f32.bf16.bf16.f32 "
                 "{%0,%1,%2,%3}, {%4,%5,%6,%7}, {%8,%9}, {%0,%1,%2,%3};"
                 : "+f"(d[0]), "+f"(d[1]), "+f"(d[2]), "+f"(d[3])
                 : "r"(a[0]), "r"(a[1]), "r"(a[2]), "r"(a[3]), "r"(b[0]), "r"(b[1]));
}
__device__ __forceinline__ uint32_t smem_u32(const void* p) {
    uint32_t a;
    asm("{ .reg .u64 t; cvta.to.shared.u64 t, %1; cvt.u32.u64 %0, t; }" : "=r"(a) : "l"(p));
    return a;
}
#define CP_ASYNC16(sa, g) asm volatile("cp.async.cg.shared.global [%0], [%1], 16;" :: "r"(sa), "l"(g))
#define CP_COMMIT()       asm volatile("cp.async.commit_group;")
#define CP_WAIT1()        asm volatile("cp.async.wait_group 1;")
#define CP_WAIT0()        asm volatile("cp.async.wait_group 0;")

// ---- launch 1: X -> bf16 fragment-ordered XA ----
// per k32 block: unit = wm*8 + mi*2 + kk (16 units, wm 0..1), uint4 = (a0,a1,a2,a3)
__global__ void prep_x_kernel(const float* __restrict__ X) {
    const int by = blockIdx.x >> 4, kb = blockIdx.x & 15;
    const int lane = threadIdx.x & 31;
    const int lq = lane >> 2, lr = lane & 3;
    #pragma unroll
    for (int h = 0; h < 4; h++) {
        const int unit = (threadIdx.x >> 5) + h * 4;    // 0..15
        const int wm = unit >> 3, mi = (unit >> 1) & 3, kk = unit & 1;
        const int r0 = by * TILE_M + wm * 64 + mi * 16 + lq;
        const int k0 = kb * 32 + kk * 16 + 2 * lr;
        const float* xr0 = X + (size_t)r0 * DIM;
        const float* xr8 = X + (size_t)(r0 + 8) * DIM;
        uint4 v;
        v.x = bf16x2(xr0[k0], xr0[k0 + 1]);
        v.y = bf16x2(xr8[k0], xr8[k0 + 1]);
        v.z = bf16x2(xr0[k0 + 8], xr0[k0 + 9]);
        v.w = bf16x2(xr8[k0 + 8], xr8[k0 + 9]);
        XA[((size_t)by * NKB32 + kb) * 512 + unit * 32 + lane] = v;
    }
}

// ---- launch 2: E -> bf16 fragment-ordered EB (64x64 warp tiles, wn 0..1) ----
// per k32 block: unit = wn*8 + njq*2 + kk (16 units), uint4 covers nj = 2*njq, 2*njq+1
__global__ void prep_e_kernel(const float* __restrict__ E) {
    const int bx = blockIdx.x >> 4, kb = blockIdx.x & 15;
    const int lane = threadIdx.x & 31;
    const int lq = lane >> 2, lr = lane & 3;
    #pragma unroll
    for (int h = 0; h < 4; h++) {
        const int unit = (threadIdx.x >> 5) + h * 4;    // 0..15
        const int wn = unit >> 3, njq = (unit >> 1) & 3, kk = unit & 1;
        const int ce = bx * TILE_N + wn * 64 + (2 * njq) * 8 + lq;
        const int co = ce + 8;
        const int k0 = kb * 32 + kk * 16 + 2 * lr;
        uint4 v;
        v.x = bf16x2(E[(size_t)k0 * NE + ce], E[(size_t)(k0 + 1) * NE + ce]);
        v.y = bf16x2(E[(size_t)(k0 + 8) * NE + ce], E[(size_t)(k0 + 9) * NE + ce]);
        v.z = bf16x2(E[(size_t)k0 * NE + co], E[(size_t)(k0 + 1) * NE + co]);
        v.w = bf16x2(E[(size_t)(k0 + 8) * NE + co], E[(size_t)(k0 + 9) * NE + co]);
        EB[((size_t)bx * NKB32 + kb) * 512 + unit * 32 + lane] = v;
    }
}

// ---- launch 3: transpose + init rowmin/candcnt + xnorm + enorm ----
__global__ void misc_prep_kernel(const float* __restrict__ X, const float* __restrict__ E) {
    const int b = blockIdx.x;
    const int tid = threadIdx.x;
    if (b < 4096) {
        __shared__ float t[32][33];
        const int j0 = (b & 255) * 32, d0 = (b >> 8) * 32;
        const int tx = tid & 31, ty = tid >> 5;
        #pragma unroll
        for (int r = 0; r < 32; r += 8)
            t[ty + r][tx] = E[(size_t)(d0 + ty + r) * NE + j0 + tx];
        __syncthreads();
        #pragma unroll
        for (int r = 0; r < 32; r += 8)
            g_embedT[(size_t)(j0 + ty + r) * DIM + d0 + tx] = t[tx][ty + r];
    } else if (b < 4224) {
        const int i = (b - 4096) * 256 + tid;
        g_rowmin[i] = 0xFFFFFFFFFFFFFFFFULL;
        g_candcnt[i] = 0;
    } else if (b < 8320) {
        const int row = (b - 4224) * 8 + (tid >> 5);
        const int lane = tid & 31;
        const float4* xr = (const float4*)(X + (size_t)row * DIM);
        float s = 0.f;
        #pragma unroll
        for (int i = lane; i < DIM / 4; i += 32) {
            float4 v = xr[i];
            s += v.x * v.x + v.y * v.y + v.z * v.z + v.w * v.w;
        }
        #pragma unroll
        for (int o = 16; o; o >>= 1) s += __shfl_down_sync(0xffffffffu, s, o);
        if (lane == 0) g_xnorm[row] = s;
    } else {
        const int j = (b - 8320) * 256 + tid;
        float s = 0.f;
        for (int d = 0; d < DIM; ++d) {
            float v = E[(size_t)d * NE + j];
            s += v * v;
        }
        g_enorm[j] = s;
    }
}

// ---- launch 4: bf16 GEMM 128x128, 4 warps of 64x64, 2-stage, 3 CTA/SM target ----
// stage layout: A [0,16KB) = two k32 halves of 8KB; B [16KB,32KB) = two k32 halves
__device__ __forceinline__ void issue_stage(uint32_t sm_stage, const uint4* ga,
                                            const uint4* gb, int tid) {
    #pragma unroll
    for (int c = 0; c < 8; c++)
        CP_ASYNC16(sm_stage + (tid + c * 128) * 16, ga + tid + c * 128);
    #pragma unroll
    for (int c = 0; c < 8; c++)
        CP_ASYNC16(sm_stage + 16384 + (tid + c * 128) * 16, gb + tid + c * 128);
    CP_COMMIT();
}

__global__ void __launch_bounds__(128, 3) gemm_mma_kernel(float* __restrict__ distp) {
    extern __shared__ char smraw[];
    unsigned long long* smin = (unsigned long long*)(smraw + SM_SMIN_OFF);
    float* sdata = (float*)(smraw + SM_DATA_OFF);
    const uint32_t smb = smem_u32(smraw) + SM_DATA_OFF;

    const int tid = threadIdx.x;
    const int wid = tid >> 5;
    const int lane = tid & 31;
    const int wm = wid & 1;          // 2 warp-rows of 64
    const int wn = wid >> 1;         // 2 warp-cols of 64
    const int browg = blockIdx.y * TILE_M;
    const int bcolg = blockIdx.x * TILE_N;
    const int lq = lane >> 2;
    const int lr = lane & 3;

    // per iteration we consume 2 k32 blocks = 1024 uint4 of A and of B
    const uint4* ga = XA + (size_t)blockIdx.y * NKB32 * 512;
    const uint4* gb = EB + (size_t)blockIdx.x * NKB32 * 512;

    float d[4][8][4];
    #pragma unroll
    for (int mi = 0; mi < 4; mi++)
        #pragma unroll
        for (int nj = 0; nj < 8; nj++)
            #pragma unroll
            for (int c = 0; c < 4; c++) d[mi][nj][c] = 0.f;

    issue_stage(smb, ga, gb, tid);
    issue_stage(smb + STAGE_BYTES, ga + 1024, gb + 1024, tid);

    const uint32_t abase = (uint32_t)(wm * 8 * 32 + lane) * 16;   // + kh*8192 + (mi*2+kk)*512
    const uint32_t bbase = (uint32_t)(wn * 8 * 32 + lane) * 16;   // + 16384 + kh*8192 + (njq*2+kk)*512

    #pragma unroll 1
    for (int i = 0; i < NITER; ++i) {
        CP_WAIT1();               // oldest group (stage i) complete
        __syncthreads();

        const char* stg = (const char*)sdata + (i & 1) * STAGE_BYTES;
        #pragma unroll
        for (int kh = 0; kh < 2; ++kh) {
            const char* ah = stg + kh * 8192;
            const char* bh_half = stg + 16384 + kh * 8192;
            #pragma unroll
            for (int kk = 0; kk < 2; ++kk) {
                uint32_t bh[8][2];
                #pragma unroll
                for (int njq = 0; njq < 4; njq++) {
                    const uint4 p = *(const uint4*)(bh_half + bbase + (njq * 2 + kk) * 512);
                    bh[2 * njq][0] = p.x; bh[2 * njq][1] = p.y;
                    bh[2 * njq + 1][0] = p.z; bh[2 * njq + 1][1] = p.w;
                }
                #pragma unroll
                for (int mi = 0; mi < 4; mi++) {
                    const uint4 a4 = *(const uint4*)(ah + abase + (mi * 2 + kk) * 512);
                    uint32_t ar[4] = {a4.x, a4.y, a4.z, a4.w};
                    #pragma unroll
                    for (int nj = 0; nj < 8; nj++)
                        mma_bf16(d[mi][nj], ar, bh[nj]);
                }
            }
        }
        __syncthreads();          // stage buffer free for refill
        if (i + 2 < NITER)
            issue_stage(smb + (i & 1) * STAGE_BYTES,
                        ga + (size_t)(i + 2) * 1024, gb + (size_t)(i + 2) * 1024, tid);
    }
    CP_WAIT0();

    // ---- epilogue: dist tile + per-row argmin ----
    smin[tid] = 0xFFFFFFFFFFFFFFFFULL;
    __syncthreads();

    float* sd = sdata;   // [col][132]
    float en8[8][2];
    #pragma unroll
    for (int nj = 0; nj < 8; nj++)
        #pragma unroll
        for (int cc = 0; cc < 2; cc++)
            en8[nj][cc] = g_enorm[bcolg + wn * 64 + nj * 8 + 2 * lr + cc];

    #pragma unroll
    for (int mi = 0; mi < 4; mi++) {
        #pragma unroll
        for (int h = 0; h < 2; h++) {
            const int row_local = wm * 64 + mi * 16 + lq + h * 8;
            const float xn = g_xnorm[browg + row_local];
            float best = 3.4e38f;
            int bcol = NE;
            #pragma unroll
            for (int nj = 0; nj < 8; nj++) {
                #pragma unroll
                for (int cc = 0; cc < 2; cc++) {
                    const int col_local = wn * 64 + nj * 8 + 2 * lr + cc;
                    const float dval = fmaf(-2.f, d[mi][nj][h * 2 + cc], xn) + en8[nj][cc];
                    sd[col_local * 132 + row_local] = dval;
                    if (dval < best) { best = dval; bcol = bcolg + col_local; }
                }
            }
            atomicMin(&smin[row_local],
                      ((unsigned long long)__float_as_uint(best) << 32) | (unsigned)bcol);
        }
    }
    __syncthreads();

    atomicMin(&g_rowmin[browg + tid], smin[tid]);
    __syncthreads();

    // ---- candidate capture vs running global min (superset of final-margin set) ----
    {
        const int grow = browg + tid;   // 1 thread per row
        const unsigned long long cur = atomicMin(&g_rowmin[grow], 0xFFFFFFFFFFFFFFFFULL);
        const float thr = __uint_as_float((unsigned)(cur >> 32)) + MARGIN;
        #pragma unroll 4
        for (int c = 0; c < TILE_N; ++c) {
            const float v = sd[c * 132 + tid];
            if (v <= thr) {
                const int s = atomicAdd(&g_candcnt[grow], 1);
                if (s < CAP) g_candbuf[(size_t)grow * CAP + s] = bcolg + c;
            }
        }
    }
    __syncthreads();

    if (distp) {
        float* dbase = distp + (size_t)browg * NE + bcolg;
        #pragma unroll 4
        for (int j = 0; j < TILE_M; ++j)
            dbase[(size_t)j * NE + tid] = sd[tid * 132 + j];
    }
}

// ---- launch 5: fused exact fp32 rescore + gather + per-row loss ----
__global__ void rescore_gather_kernel(const float* __restrict__ X,
                                      const float* __restrict__ distp,
                                      float* __restrict__ qp,
                                      float* __restrict__ indp) {
    const int row = blockIdx.x;
    const int tid = threadIdx.x;   // 128
    __shared__ int cand[CAP];
    __shared__ int scount;
    __shared__ float red[128];
    __shared__ unsigned long long sbest;

    // --- rescore phase ---
    int n = g_candcnt[row];
    if (n <= CAP) {
        for (int i = tid; i < n; i += 128) cand[i] = g_candbuf[(size_t)row * CAP + i];
        if (tid == 0) sbest = 0xFFFFFFFFFFFFFFFFULL;
        __syncthreads();
    } else {
        if (tid == 0) { scount = 0; sbest = 0xFFFFFFFFFFFFFFFFULL; }
        __syncthreads();
        const float thr = __uint_as_float((unsigned)(g_rowmin[row] >> 32)) + MARGIN;
        if (distp) {
            const float* dr = distp + (size_t)row * NE;
            for (int i = tid; i < NE; i += 128) {
                if (dr[i] <= thr) {
                    const int s = atomicAdd(&scount, 1);
                    if (s < CAP) cand[s] = i;
                }
            }
        } else if (tid == 0) scount = 0;
        __syncthreads();
        n = scount < CAP ? scount : CAP;
    }

    const float xn = g_xnorm[row];
    const float4 x = ((const float4*)(X + (size_t)row * DIM))[tid];
    for (int c = 0; c < n; ++c) {
        const int col = cand[c];
        const float4 ev = ((const float4*)(g_embedT + (size_t)col * DIM))[tid];
        red[tid] = x.x * ev.x + x.y * ev.y + x.z * ev.z + x.w * ev.w;
        __syncthreads();
        #pragma unroll
        for (int s = 64; s; s >>= 1) {
            if (tid < s) red[tid] += red[tid + s];
            __syncthreads();
        }
        if (tid == 0) {
            const float dv = fmaf(-2.f, red[0], xn) + g_enorm[col];
            const unsigned long long pk =
                ((unsigned long long)__float_as_uint(dv) << 32) | (unsigned)col;
            if (pk < sbest) sbest = pk;
        }
        __syncthreads();
    }

    // --- gather phase ---
    const unsigned long long pk = (n > 0) ? sbest : g_rowmin[row];
    const unsigned ind = (unsigned)(pk & 0xFFFFFFFFu);
    if (indp && tid == 0) indp[row] = (float)ind;

    const float4 q = ((const float4*)(g_embedT + (size_t)ind * DIM))[tid];
    if (qp) {
        float4 o;
        o.x = x.x + (q.x - x.x); o.y = x.y + (q.y - x.y);
        o.z = x.z + (q.z - x.z); o.w = x.w + (q.w - x.w);
        ((float4*)(qp + (size_t)row * DIM))[tid] = o;
    }
    float dx = x.x - q.x, dy = x.y - q.y, dz = x.z - q.z, dw = x.w - q.w;
    red[tid] = dx * dx + dy * dy + dz * dz + dw * dw;
    __syncthreads();
    #pragma unroll
    for (int s = 64; s; s >>= 1) {
        if (tid < s) red[tid] += red[tid + s];
        __syncthreads();
    }
    if (tid == 0) g_rowloss[row] = red[0];
}

__global__ void loss_kernel(float* __restrict__ lossp) {
    __shared__ float red[512];
    const int tid = threadIdx.x;
    float s = 0.f;
    for (int i = tid; i < NT; i += 512) s += g_rowloss[i];
    red[tid] = s;
    __syncthreads();
    #pragma unroll
    for (int st = 256; st; st >>= 1) {
        if (tid < st) red[tid] += red[tid + st];
        __syncthreads();
    }
    if (tid == 0) *lossp = red[0] * (1.0f / ((float)NT * (float)DIM));
}

extern "C" void kernel_launch(void* const* d_in, const int* in_sizes, int n_in,
                              void* d_out, int out_size) {
    const float* X = (const float*)d_in[0];
    const float* E = (const float*)d_in[1];
    float* out = (float*)d_out;

    const long long QN = (long long)NT * DIM;
    const long long DN = (long long)NT * NE;
    const long long OS = (long long)out_size;

    float *qp = 0, *indp = 0, *lossp = 0, *distp = 0;
    if (OS == QN + NT + 1 + DN) {
        qp = out; indp = out + QN; lossp = out + QN + NT; distp = out + QN + NT + 1;
    } else if (OS == QN) { qp = out;
    } else if (OS == DN) { distp = out;
    } else if (OS == NT) { indp = out;
    } else if (OS == 1)  { lossp = out;
    } else if (OS == QN + NT + 1) { qp = out; indp = out + QN; lossp = out + QN + NT;
    } else {
        if (OS >= QN) qp = out;
        if (OS >= QN + NT) indp = out + QN;
        if (OS >= QN + NT + 1) lossp = out + QN + NT;
        if (OS >= QN + NT + 1 + DN) distp = out + QN + NT + 1;
    }

    cudaFuncSetAttribute(gemm_mma_kernel, cudaFuncAttributeMaxDynamicSharedMemorySize, SMEM_TOTAL);

    prep_x_kernel<<<NBY * NKB32, 128>>>(X);                      // 1
    prep_e_kernel<<<NBX * NKB32, 128>>>(E);                      // 2
    misc_prep_kernel<<<8352, 256>>>(X, E);                       // 3
    gemm_mma_kernel<<<dim3(NBX, NBY), 128, SMEM_TOTAL>>>(distp); // 4 (ncu slot)
    rescore_gather_kernel<<<NT, 128>>>(X, distp, qp, indp);      // 5
    if (lossp) loss_kernel<<<1, 512>>>(lossp);                   // 6
}